// round 15
// baseline (speedup 1.0000x reference)
#include <cuda_runtime.h>
#include <math.h>

// Problem constants
#define B 32
#define S 2048
#define D 1024
#define MASK_PENALTY 100000000.0f

// Tiling
#define NSPLIT 16
#define WARPS 4
#define THREADS (WARPS * 32)                    // 128
#define ROWS_PER_SPLIT (S / NSPLIT)             // 128 == THREADS
#define NSLOTS 3                                // per-warp ring depth (pairs)
#define ROW_BYTES (D * 4)                       // 4096
#define SLOT_BYTES (2 * ROW_BYTES)              // 8192: one PAIR per slot

#define SLOTS_BYTES (WARPS * NSLOTS * SLOT_BYTES)   // 96 KB dynamic smem

// Scratch (allocation-free: __device__ globals, zero-init)
__device__ float g_m[B * NSPLIT];
__device__ float g_l[B * NSPLIT];
__device__ __align__(16) float g_acc[(size_t)B * NSPLIT * D];  // 2 MB
__device__ int g_cnt[B];  // zero-init; self-resets each launch

// ---- mbarrier / bulk-copy helpers ----
__device__ __forceinline__ unsigned smem_u32(const void* p) {
    return (unsigned)__cvta_generic_to_shared(p);
}
__device__ __forceinline__ void mbar_init(unsigned mbar, unsigned count) {
    asm volatile("mbarrier.init.shared.b64 [%0], %1;" :: "r"(mbar), "r"(count)
                 : "memory");
}
__device__ __forceinline__ void mbar_expect_tx(unsigned mbar, unsigned bytes) {
    asm volatile("mbarrier.arrive.expect_tx.shared.b64 _, [%0], %1;"
                 :: "r"(mbar), "r"(bytes) : "memory");
}
__device__ __forceinline__ void mbar_wait(unsigned mbar, unsigned phase) {
    asm volatile(
        "{\n\t.reg .pred P;\n\t"
        "WL_%=:\n\t"
        "mbarrier.try_wait.parity.acquire.cta.shared::cta.b64 P, [%0], %1, 0x989680;\n\t"
        "@!P bra WL_%=;\n\t"
        "}" :: "r"(mbar), "r"(phase) : "memory");
}
__device__ __forceinline__ void bulk_cp(unsigned dst, const void* src,
                                        unsigned bytes, unsigned mbar) {
    asm volatile(
        "cp.async.bulk.shared::cluster.global.mbarrier::complete_tx::bytes "
        "[%0], [%1], %2, [%3];"
        :: "r"(dst), "l"(src), "r"(bytes), "r"(mbar) : "memory");
}

// ---------------------------------------------------------------------------
// Fused single-pass online-softmax attention: mask skipping + compaction +
// per-warp bulk-copy ring with RUN-COALESCED 8KB REQUESTS.
// Each ring slot holds a PAIR of valid rows. When the pair is address-
// adjacent (~50% at mask density 1/2) it is fetched with ONE 8KB bulk copy;
// otherwise two 4KB copies land on the same mbarrier (expect_tx accumulates).
// Grows mean DRAM request size with zero extra bytes. One combined softmax
// update per pair halves the serial exp/rescale windows.
// 4 warp partials merge in smem (ring reused) -> 1 per CTA -> last CTA per
// batch merges the NSPLIT split partials (no second kernel).
// ---------------------------------------------------------------------------
__global__ void __launch_bounds__(THREADS)
attn_fused(const float* __restrict__ target,
           const float* __restrict__ context,
           const float* __restrict__ mask,
           float* __restrict__ out)
{
    extern __shared__ __align__(128) char slots[];   // [WARPS][NSLOTS][8192]

    const int b     = blockIdx.x;
    const int split = blockIdx.y;
    const int w     = threadIdx.x >> 5;
    const int lane  = threadIdx.x & 31;
    const int s0    = split * ROWS_PER_SPLIT;

    __shared__ __align__(8) unsigned long long mbar_s[WARPS][NSLOTS];
    __shared__ short slist[ROWS_PER_SPLIT];
    __shared__ int   swcnt[WARPS];
    __shared__ int   scnt;
    __shared__ float sm_[WARPS];
    __shared__ float sl_[WARPS];

    // ---- Barrier init + deterministic compaction (128 threads, 1 row each)
    if (threadIdx.x < WARPS * NSLOTS)
        mbar_init(smem_u32(&mbar_s[threadIdx.x / NSLOTS][threadIdx.x % NSLOTS]), 1);

    const bool v = mask[(size_t)b * S + s0 + threadIdx.x] != 0.f;
    const unsigned bal = __ballot_sync(0xffffffffu, v);
    if (lane == 0) swcnt[w] = __popc(bal);
    __syncthreads();

    if (threadIdx.x == 0)
        scnt = swcnt[0] + swcnt[1] + swcnt[2] + swcnt[3];
    if (v) {
        int off = 0;
#pragma unroll
        for (int i = 0; i < WARPS; i++) off += (i < w) ? swcnt[i] : 0;
        const int pos = off + __popc(bal & ((1u << lane) - 1u));
        slist[pos] = (short)threadIdx.x;
    }

    // Lane's slice of the query vector (registers)
    const float4* tg = (const float4*)(target + (size_t)b * D);
    float4 t[8];
#pragma unroll
    for (int i = 0; i < 8; i++) t[i] = tg[lane + 32 * i];

    __syncthreads();
    const int cnt = scnt;
    const float* cb = context + (size_t)b * S * D;

    // Per-warp contiguous chunk of the compacted list (ascending addresses)
    const int begin = (cnt * w) / WARPS;
    const int end   = (cnt * (w + 1)) / WARPS;
    const int npw   = (end - begin + 1) >> 1;     // pairs in this chunk

    // This warp's ring
    char* wslot = slots + (size_t)w * NSLOTS * SLOT_BYTES;
    const unsigned slot_u32 = smem_u32(wslot);
    unsigned mb[NSLOTS];
#pragma unroll
    for (int k = 0; k < NSLOTS; k++) mb[k] = smem_u32(&mbar_s[w][k]);

    // Fill slot `slot` with pair index k (lane 0 only)
    auto fill = [&](int k, int slot) {
        const int pi = begin + 2 * k;
        const int r1 = slist[pi];
        const bool has2 = (pi + 1 < end);
        const unsigned dst = slot_u32 + slot * SLOT_BYTES;
        mbar_expect_tx(mb[slot], has2 ? (unsigned)SLOT_BYTES : (unsigned)ROW_BYTES);
        if (has2) {
            const int r2 = slist[pi + 1];
            if (r2 == r1 + 1) {
                // run-coalesced: ONE 8KB request
                bulk_cp(dst, cb + (size_t)(s0 + r1) * D, SLOT_BYTES, mb[slot]);
            } else {
                bulk_cp(dst, cb + (size_t)(s0 + r1) * D, ROW_BYTES, mb[slot]);
                bulk_cp(dst + ROW_BYTES, cb + (size_t)(s0 + r2) * D, ROW_BYTES,
                        mb[slot]);
            }
        } else {
            bulk_cp(dst, cb + (size_t)(s0 + r1) * D, ROW_BYTES, mb[slot]);
        }
    };

    // Prologue: issue the first NSLOTS pairs
    if (lane == 0) {
#pragma unroll
        for (int k = 0; k < NSLOTS; k++)
            if (k < npw) fill(k, k);
    }

    float4 acc[8];
#pragma unroll
    for (int i = 0; i < 8; i++) acc[i] = make_float4(0.f, 0.f, 0.f, 0.f);

    float m = -INFINITY;
    float l = 0.f;

    // ---- Mainloop: one PAIR of valid rows per iteration ----
    for (int k = 0; k < npw; k++) {
        const int slot = k % NSLOTS;
        const unsigned phase = (unsigned)((k / NSLOTS) & 1);
        const bool has2 = (begin + 2 * k + 1 < end);

        mbar_wait(mb[slot], phase);

        const float4* sp1 = (const float4*)(wslot + slot * SLOT_BYTES);
        const float4* sp2 = (const float4*)(wslot + slot * SLOT_BYTES + ROW_BYTES);
        float4 c1[8], c2[8];
#pragma unroll
        for (int j = 0; j < 8; j++) c1[j] = sp1[lane + 32 * j];
        if (has2) {
#pragma unroll
            for (int j = 0; j < 8; j++) c2[j] = sp2[lane + 32 * j];
        } else {
#pragma unroll
            for (int j = 0; j < 8; j++) c2[j] = make_float4(0.f, 0.f, 0.f, 0.f);
        }

        // Refill this slot with the pair NSLOTS ahead
        const int kn = k + NSLOTS;
        if (lane == 0 && kn < npw) fill(kn, slot);

        // two interleaved dot products
        float a0 = 0.f, a1 = 0.f, b0 = 0.f, b1 = 0.f;
#pragma unroll
        for (int j = 0; j < 8; j++) {
            a0 = fmaf(c1[j].x, t[j].x, a0);
            a1 = fmaf(c1[j].y, t[j].y, a1);
            a0 = fmaf(c1[j].z, t[j].z, a0);
            a1 = fmaf(c1[j].w, t[j].w, a1);
            b0 = fmaf(c2[j].x, t[j].x, b0);
            b1 = fmaf(c2[j].y, t[j].y, b1);
            b0 = fmaf(c2[j].z, t[j].z, b0);
            b1 = fmaf(c2[j].w, t[j].w, b1);
        }
        float dot1 = a0 + a1;
        float dot2 = b0 + b1;
#pragma unroll
        for (int off = 16; off > 0; off >>= 1) {
            dot1 += __shfl_xor_sync(0xffffffffu, dot1, off);
            dot2 += __shfl_xor_sync(0xffffffffu, dot2, off);
        }
        if (!has2) dot2 = -INFINITY;

        // ONE combined online-softmax update for the pair
        const float mnew  = fmaxf(m, fmaxf(dot1, dot2));
        const float scale = __expf(m - mnew);              // 0 on first pair
        const float w1    = __expf(dot1 - mnew);
        const float w2    = has2 ? __expf(dot2 - mnew) : 0.f;
        l = l * scale + (w1 + w2);
#pragma unroll
        for (int j = 0; j < 8; j++) {
            acc[j].x = fmaf(acc[j].x, scale, fmaf(w1, c1[j].x, w2 * c2[j].x));
            acc[j].y = fmaf(acc[j].y, scale, fmaf(w1, c1[j].y, w2 * c2[j].y));
            acc[j].z = fmaf(acc[j].z, scale, fmaf(w1, c1[j].z, w2 * c2[j].z));
            acc[j].w = fmaf(acc[j].w, scale, fmaf(w1, c1[j].w, w2 * c2[j].w));
        }
        m = mnew;
    }

    // ---- In-CTA merge of the 4 warp partials (ring memory reused) ----
    if (lane == 0) { sm_[w] = m; sl_[w] = l; }
    __syncthreads();   // all warps done with their ring slots

    float Mcta = -INFINITY;
#pragma unroll
    for (int i = 0; i < WARPS; i++) Mcta = fmaxf(Mcta, sm_[i]);

    float4* sacc = (float4*)slots;   // [WARPS][D/4] = 16 KB within 96 KB
    const float f = (m > -INFINITY) ? __expf(m - Mcta) : 0.f;
#pragma unroll
    for (int i = 0; i < 8; i++) {
        float4 a = acc[i];
        a.x *= f; a.y *= f; a.z *= f; a.w *= f;
        sacc[w * (D / 4) + lane + 32 * i] = a;
    }
    __syncthreads();

    // 128 threads sum across 4 warps; each thread owns 2 float4 positions
    const int pidx = b * NSPLIT + split;
#pragma unroll
    for (int h = 0; h < 2; h++) {
        const int d4 = threadIdx.x + h * THREADS;
        float4 sum = sacc[d4];
#pragma unroll
        for (int i = 1; i < WARPS; i++) {
            const float4 vv = sacc[i * (D / 4) + d4];
            sum.x += vv.x; sum.y += vv.y; sum.z += vv.z; sum.w += vv.w;
        }
        ((float4*)(g_acc + (size_t)pidx * D))[d4] = sum;
    }

    if (threadIdx.x == 0) {
        float L = 0.f;
#pragma unroll
        for (int i = 0; i < WARPS; i++)
            L += (sm_[i] > -INFINITY ? __expf(sm_[i] - Mcta) : 0.f) * sl_[i];
        g_m[pidx] = Mcta;   // -inf if the whole split is masked
        g_l[pidx] = L;
    }

    // ---- Last CTA per batch merges the NSPLIT partials ----
    __threadfence();
    __syncthreads();
    __shared__ int isLast;
    if (threadIdx.x == 0)
        isLast = (atomicAdd(&g_cnt[b], 1) == NSPLIT - 1);
    __syncthreads();
    if (!isLast) return;
    __threadfence();  // acquire

    float pm[NSPLIT], pl[NSPLIT];
#pragma unroll
    for (int p = 0; p < NSPLIT; p++) {
        pm[p] = __ldcg(&g_m[b * NSPLIT + p]);
        pl[p] = __ldcg(&g_l[b * NSPLIT + p]);
    }
    // M is finite: position 0 of every batch is guaranteed valid.
    float M = -INFINITY;
#pragma unroll
    for (int p = 0; p < NSPLIT; p++) M = fmaxf(M, pm[p]);
    float L = 0.f;
#pragma unroll
    for (int p = 0; p < NSPLIT; p++)
        L += (pm[p] > -INFINITY ? __expf(pm[p] - M) : 0.f) * pl[p];
    const float Linv = 1.f / L;

#pragma unroll
    for (int h = 0; h < 2; h++) {
        const int d4 = threadIdx.x + h * THREADS;
        float4 a = make_float4(0.f, 0.f, 0.f, 0.f);
#pragma unroll
        for (int p = 0; p < NSPLIT; p++) {
            const float fp = (pm[p] > -INFINITY) ? __expf(pm[p] - M) : 0.f;
            const float4 vv =
                __ldcg((const float4*)(g_acc + (size_t)(b * NSPLIT + p) * D) + d4);
            a.x = fmaf(fp, vv.x, a.x);
            a.y = fmaf(fp, vv.y, a.y);
            a.z = fmaf(fp, vv.z, a.z);
            a.w = fmaf(fp, vv.w, a.w);
        }
        a.x *= Linv; a.y *= Linv; a.z *= Linv; a.w *= Linv;
        ((float4*)(out + (size_t)b * D))[d4] = a;
    }

    if (threadIdx.x == 0) atomicExch(&g_cnt[b], 0);
}

extern "C" void kernel_launch(void* const* d_in, const int* in_sizes, int n_in,
                              void* d_out, int out_size)
{
    const float* target  = (const float*)d_in[0];  // [B, D]
    const float* context = (const float*)d_in[1];  // [B, S, D]
    const float* mask    = (const float*)d_in[2];  // [B, S]
    float* out = (float*)d_out;                    // [B, D]

    cudaFuncSetAttribute(attn_fused,
                         cudaFuncAttributeMaxDynamicSharedMemorySize,
                         SLOTS_BYTES);

    dim3 grid(B, NSPLIT);
    attn_fused<<<grid, THREADS, SLOTS_BYTES>>>(target, context, mask, out);
}